// round 12
// baseline (speedup 1.0000x reference)
#include <cuda_runtime.h>
#include <math.h>

#define KS 11
#define TILE 32
#define TYB 8
#define RY 4
#define HR 42   // TILE + 10
#define SP 44   // padded float2 row stride (16B-aligned rows)

typedef unsigned long long ull;

__device__ __forceinline__ ull pk2(float lo, float hi) {
    ull r; asm("mov.b64 %0,{%1,%2};" : "=l"(r) : "f"(lo), "f"(hi)); return r;
}
__device__ __forceinline__ void upk2(ull v, float& lo, float& hi) {
    asm("mov.b64 {%0,%1},%2;" : "=f"(lo), "=f"(hi) : "l"(v));
}
__device__ __forceinline__ ull fma2(ull a, ull b, ull c) {
    ull d; asm("fma.rn.f32x2 %0,%1,%2,%3;" : "=l"(d) : "l"(a), "l"(b), "l"(c)); return d;
}
__device__ __forceinline__ ull mul2(ull a, ull b) {
    ull d; asm("mul.rn.f32x2 %0,%1,%2;" : "=l"(d) : "l"(a), "l"(b)); return d;
}
__device__ __forceinline__ float frcp(float x) {
    float r; asm("rcp.approx.f32 %0, %1;" : "=f"(r) : "f"(x)); return r;
}

__device__ constexpr float GW[KS] = {
    0.00102836f, 0.00759866f, 0.03600077f, 0.10936069f, 0.21300566f,
    0.26601190f,
    0.21300566f, 0.10936069f, 0.03600077f, 0.00759866f, 0.00102836f
};
__device__ __forceinline__ ull WPK(const ull* w, int k) {
    return w[k < 6 ? k : 10 - k];
}

// Pyramid levels in (s,d) float2 form
__device__ float2 g_P0[96 * 192 * 192];
__device__ float2 g_P1[96 * 96 * 96];
__device__ float2 g_P2[96 * 48 * 48];
__device__ float2 g_P3[96 * 24 * 24];
__device__ float g_acc[5 * 96 * 2];

__global__ void zero_acc_kernel() {
    int i = threadIdx.x;
    if (i < 5 * 96 * 2) g_acc[i] = 0.f;
}

// Pool (s,d) float2 -> half res (2 outputs/thread, float4 loads)
__global__ void pool_sd_kernel(const float2* __restrict__ in, float2* __restrict__ out,
                               int W, int n2)
{
    int i = blockIdx.x * blockDim.x + threadIdx.x;
    if (i >= n2) return;
    int ow = W >> 1, owh = ow >> 1;
    int bc = i / (ow * owh);
    int rem = i - bc * ow * owh;
    int oy = rem / owh, oxp = rem - oy * owh;
    const float2* p0 = in + (size_t)bc * W * W + (size_t)(2 * oy) * W + 4 * oxp;
    const float2* p1 = p0 + W;
    float2 a0 = p0[0], a1 = p0[1], a2 = p0[2], a3 = p0[3];
    float2 b0 = p1[0], b1 = p1[1], b2 = p1[2], b3 = p1[3];
    float2* o = out + (size_t)bc * ow * ow + (size_t)oy * ow + 2 * oxp;
    o[0] = make_float2(0.25f * (a0.x + a1.x + b0.x + b1.x),
                       0.25f * (a0.y + a1.y + b0.y + b1.y));
    o[1] = make_float2(0.25f * (a2.x + a3.x + b2.x + b3.x),
                       0.25f * (a2.y + a3.y + b2.y + b3.y));
}

// ---- R11 ssim core as a device function (tile = bx,by of image bc) ----
__device__ __forceinline__
void ssim_core(const float* __restrict__ X, const float* __restrict__ Y,
               const float2* __restrict__ SDin, float2* __restrict__ SDout,
               int W, int OW, int scale, int bx, int by, int bc)
{
    __shared__ float2 sSD[HR][SP];
    __shared__ float4 sH[HR][TILE];
    __shared__ float rs[TYB], rc[TYB];

    const int tx = threadIdx.x, ty = threadIdx.y;
    const int t = ty * 32 + tx;
    const int x0 = bx * TILE, y0 = by * TILE;
    const bool interior = (x0 + HR <= W) && (y0 + HR <= W);

    if (SDin) {
        const float2* Sb = SDin + (size_t)bc * W * W;
        if (interior) {
            for (int i = t; i < HR * 21; i += 256) {
                int r = i / 21, cp = (i - r * 21) * 2;
                float4 v = *(const float4*)&Sb[(size_t)(y0 + r) * W + x0 + cp];
                *(float4*)&sSD[r][cp] = v;
            }
        } else {
            for (int idx = t; idx < HR * HR; idx += 256) {
                int r = idx / HR, c = idx - r * HR;
                int gx = x0 + c, gy = y0 + r;
                float2 v = make_float2(0.f, 0.f);
                if (gx < W && gy < W) v = Sb[(size_t)gy * W + gx];
                sSD[r][c] = v;
            }
        }
    } else {
        const float* Xb = X + (size_t)bc * W * W;
        const float* Yb = Y + (size_t)bc * W * W;
        if (interior) {
            for (int i = t; i < HR * 21; i += 256) {
                int r = i / 21, cp = (i - r * 21) * 2;
                size_t o = (size_t)(y0 + r) * W + x0 + cp;
                float2 xv = *(const float2*)(Xb + o);
                float2 yv = *(const float2*)(Yb + o);
                float4 v = make_float4(xv.x + yv.x, xv.x - yv.x,
                                       xv.y + yv.y, xv.y - yv.y);
                *(float4*)&sSD[r][cp] = v;
            }
        } else {
            for (int idx = t; idx < HR * HR; idx += 256) {
                int r = idx / HR, c = idx - r * HR;
                int gx = x0 + c, gy = y0 + r;
                float xv = 0.f, yv = 0.f;
                if (gx < W && gy < W) {
                    size_t o = (size_t)gy * W + gx;
                    xv = Xb[o]; yv = Yb[o];
                }
                sSD[r][c] = make_float2(xv + yv, xv - yv);
            }
        }
    }
    __syncthreads();

    if (SDout) {
        int W2 = W >> 1;
        int cx = t & 15, cy = t >> 4;
        int gx2 = (x0 >> 1) + cx, gy2 = (y0 >> 1) + cy;
        if (gx2 < W2 && gy2 < W2) {
            float2 a = sSD[2 * cy][2 * cx],     b = sSD[2 * cy][2 * cx + 1];
            float2 c = sSD[2 * cy + 1][2 * cx], d = sSD[2 * cy + 1][2 * cx + 1];
            float2 o;
            o.x = 0.25f * (a.x + b.x + c.x + d.x);
            o.y = 0.25f * (a.y + b.y + c.y + d.y);
            SDout[(size_t)bc * W2 * W2 + (size_t)gy2 * W2 + gx2] = o;
        }
    }

    ull wpk[6];
    #pragma unroll
    for (int k = 0; k < 6; k++) wpk[k] = pk2(GW[k], GW[k]);

    // h-pass: warp = 2 rows x 16 lane-pairs, aligned LDS.128, permuted stores
    {
        const int half = tx >> 4;
        const int j = tx & 15;
        #pragma unroll
        for (int rp = 0; rp < HR / 2; rp += TYB) {
            int p = rp + ty;
            if (p < HR / 2) {
                const int r = 2 * p + half;
                ull s0 = 0ULL, q0 = 0ULL, s1 = 0ULL, q1 = 0ULL;
                #pragma unroll
                for (int m = 0; m < 6; m++) {
                    float4 v = *(const float4*)&sSD[r][2 * j + 2 * m];
                    ull pa = pk2(v.x, v.y), pb = pk2(v.z, v.w);
                    ull qa = mul2(pa, pa),  qb = mul2(pb, pb);
                    s0 = fma2(pa, WPK(wpk, 2 * m), s0);
                    q0 = fma2(qa, WPK(wpk, 2 * m), q0);
                    s1 = fma2(pb, WPK(wpk, 2 * m), s1);
                    q1 = fma2(qb, WPK(wpk, 2 * m), q1);
                    if (m < 5) {
                        s0 = fma2(pb, WPK(wpk, 2 * m + 1), s0);
                        q0 = fma2(qb, WPK(wpk, 2 * m + 1), q0);
                    }
                    if (m > 0) {
                        s1 = fma2(pa, WPK(wpk, 2 * m - 1), s1);
                        q1 = fma2(qa, WPK(wpk, 2 * m - 1), q1);
                    }
                }
                float b0, b1, b2, b3;
                upk2(s0, b0, b1); upk2(q0, b2, b3);
                sH[r][j] = make_float4(b0, b1, b2, b3);
                upk2(s1, b0, b1); upk2(q1, b2, b3);
                sH[r][16 + j] = make_float4(b0, b1, b2, b3);
            }
        }
    }
    __syncthreads();

    // v-pass + ssim, RY=4 (permuted columns)
    ull amu[RY], asg[RY];
    #pragma unroll
    for (int jj = 0; jj < RY; jj++) { amu[jj] = 0ULL; asg[jj] = 0ULL; }
    const int rbase = ty * RY;
    #pragma unroll
    for (int rr = 0; rr < RY - 1 + KS; rr++) {
        float4 u = sH[rbase + rr][tx];
        ull p01 = pk2(u.x, u.y), p23 = pk2(u.z, u.w);
        #pragma unroll
        for (int jj = 0; jj < RY; jj++) {
            int k = rr - jj;
            if (k >= 0 && k < KS) {
                amu[jj] = fma2(p01, WPK(wpk, k), amu[jj]);
                asg[jj] = fma2(p23, WPK(wpk, k), asg[jj]);
            }
        }
    }

    float ssum = 0.f, csum = 0.f;
    const int lc = (tx < 16) ? (2 * tx) : (2 * (tx - 16) + 1);
    const int ox = x0 + lc;
    #pragma unroll
    for (int jj = 0; jj < RY; jj++) {
        int oy = y0 + rbase + jj;
        if (ox < OW && oy < OW) {
            float ms2, md2, bss, bdd;
            upk2(mul2(amu[jj], amu[jj]), ms2, md2);
            upk2(asg[jj], bss, bdd);
            const float C1 = 6.5025f, C2 = 58.5225f;
            float musum  = 0.5f * (ms2 + md2);
            float mu2x   = 0.5f * (ms2 - md2);
            float sqsum  = 0.5f * (bss + bdd);
            float xy2    = 0.5f * (bss - bdd);
            float A  = (xy2 - mu2x) + C2;
            float B  = (sqsum - musum) + C2;
            float Cn = mu2x + C1;
            float D  = musum + C1;
            float inv = frcp(B * D);
            csum += A * D * inv;
            ssum += A * Cn * inv;
        }
    }

    #pragma unroll
    for (int off = 16; off; off >>= 1) {
        ssum += __shfl_down_sync(0xffffffffu, ssum, off);
        csum += __shfl_down_sync(0xffffffffu, csum, off);
    }
    if (tx == 0) { rs[ty] = ssum; rc[ty] = csum; }
    __syncthreads();
    if (t == 0) {
        float a = 0.f, b = 0.f;
        #pragma unroll
        for (int i = 0; i < TYB; i++) { a += rs[i]; b += rc[i]; }
        atomicAdd(&g_acc[(scale * 96 + bc) * 2 + 0], a);
        atomicAdd(&g_acc[(scale * 96 + bc) * 2 + 1], b);
    }
}

// scale-0 kernel (fused pool -> P0)
__global__ __launch_bounds__(256)
void ssim0_kernel(const float* __restrict__ X, const float* __restrict__ Y,
                  float2* __restrict__ P0)
{
    ssim_core(X, Y, nullptr, P0, 384, 374, 0, blockIdx.x, blockIdx.y, blockIdx.z);
}

// merged scales 1-4, 1-D grid: [0,3456) s1 | [3456,4320) s2 | [4320,4704) s3 | [4704,4800) s4
__global__ __launch_bounds__(256)
void ssim_rest_kernel(const float2* __restrict__ P0, const float2* __restrict__ P1,
                      const float2* __restrict__ P2, const float2* __restrict__ P3)
{
    int b = blockIdx.x;
    if (b < 3456) {
        ssim_core(nullptr, nullptr, P0, nullptr, 192, 182, 1, b % 6, (b / 6) % 6, b / 36);
    } else if (b < 4320) {
        b -= 3456;
        ssim_core(nullptr, nullptr, P1, nullptr, 96, 86, 2, b % 3, (b / 3) % 3, b / 9);
    } else if (b < 4704) {
        b -= 4320;
        ssim_core(nullptr, nullptr, P2, nullptr, 48, 38, 3, b % 2, (b / 2) % 2, b / 4);
    } else {
        b -= 4704;
        ssim_core(nullptr, nullptr, P3, nullptr, 24, 14, 4, 0, 0, b);
    }
}

__global__ void finalize_kernel(float* __restrict__ out) {
    __shared__ float sh[96];
    const int i = threadIdx.x;
    const float wts[5]  = {0.0448f, 0.2856f, 0.3001f, 0.2363f, 0.1333f};
    const float cnts[5] = {374.f * 374.f, 182.f * 182.f, 86.f * 86.f, 38.f * 38.f, 14.f * 14.f};
    if (i < 96) {
        float p = 1.f;
        #pragma unroll
        for (int s = 0; s < 5; s++) {
            int comp = (s < 4) ? 1 : 0;
            float m = g_acc[(s * 96 + i) * 2 + comp] / cnts[s];
            m = fmaxf(m, 0.f);
            p *= powf(m, wts[s]);
        }
        sh[i] = p;
    }
    __syncthreads();
    if (i == 0) {
        float s = 0.f;
        for (int j = 0; j < 96; j++) s += sh[j];
        out[0] = 1.f - s / 96.f;
    }
}

extern "C" void kernel_launch(void* const* d_in, const int* in_sizes, int n_in,
                              void* d_out, int out_size)
{
    const float* X = (const float*)d_in[0];
    const float* Y = (const float*)d_in[1];
    float* out = (float*)d_out;

    float2 *P0, *P1, *P2, *P3;
    cudaGetSymbolAddress((void**)&P0, g_P0);
    cudaGetSymbolAddress((void**)&P1, g_P1);
    cudaGetSymbolAddress((void**)&P2, g_P2);
    cudaGetSymbolAddress((void**)&P3, g_P3);

    zero_acc_kernel<<<1, 960>>>();

    dim3 blk(32, TYB);

    // scale 0 (pools 192^2 into P0 in its epilogue)
    ssim0_kernel<<<dim3(12, 12, 96), blk>>>(X, Y, P0);

    // tiny pool chain builds P1, P2, P3
    int n2 = 96 * 96 * 96 / 2;
    pool_sd_kernel<<<(n2 + 255) / 256, 256>>>(P0, P1, 192, n2);
    int n3 = 96 * 48 * 48 / 2;
    pool_sd_kernel<<<(n3 + 255) / 256, 256>>>(P1, P2, 96, n3);
    int n4 = 96 * 24 * 24 / 2;
    pool_sd_kernel<<<(n4 + 255) / 256, 256>>>(P2, P3, 48, n4);

    // scales 1-4 concurrently in one launch
    ssim_rest_kernel<<<4800, blk>>>(P0, P1, P2, P3);

    finalize_kernel<<<1, 96>>>(out);
}

// round 13
// speedup vs baseline: 1.0136x; 1.0136x over previous
#include <cuda_runtime.h>
#include <math.h>

#define KS 11
#define TILE 32
#define TYB 8
#define RY 4
#define HR 42   // TILE + 10
#define SP 44   // padded float2 row stride (16B-aligned rows)

typedef unsigned long long ull;

__device__ __forceinline__ ull pk2(float lo, float hi) {
    ull r; asm("mov.b64 %0,{%1,%2};" : "=l"(r) : "f"(lo), "f"(hi)); return r;
}
__device__ __forceinline__ void upk2(ull v, float& lo, float& hi) {
    asm("mov.b64 {%0,%1},%2;" : "=f"(lo), "=f"(hi) : "l"(v));
}
__device__ __forceinline__ ull fma2(ull a, ull b, ull c) {
    ull d; asm("fma.rn.f32x2 %0,%1,%2,%3;" : "=l"(d) : "l"(a), "l"(b), "l"(c)); return d;
}
__device__ __forceinline__ ull mul2(ull a, ull b) {
    ull d; asm("mul.rn.f32x2 %0,%1,%2;" : "=l"(d) : "l"(a), "l"(b)); return d;
}
__device__ __forceinline__ float frcp(float x) {
    float r; asm("rcp.approx.f32 %0, %1;" : "=f"(r) : "f"(x)); return r;
}
// Direct packed smem access: LDS.128 / STS.128 straight into aligned 64-bit pairs
__device__ __forceinline__ void lds2(ull& a, ull& b, const void* p) {
    unsigned addr = (unsigned)__cvta_generic_to_shared(p);
    asm("ld.shared.v2.u64 {%0,%1}, [%2];" : "=l"(a), "=l"(b) : "r"(addr));
}
__device__ __forceinline__ void sts2(void* p, ull a, ull b) {
    unsigned addr = (unsigned)__cvta_generic_to_shared(p);
    asm("st.shared.v2.u64 [%0], {%1,%2};" :: "r"(addr), "l"(a), "l"(b));
}

__device__ constexpr float GW[KS] = {
    0.00102836f, 0.00759866f, 0.03600077f, 0.10936069f, 0.21300566f,
    0.26601190f,
    0.21300566f, 0.10936069f, 0.03600077f, 0.00759866f, 0.00102836f
};
__device__ __forceinline__ ull WPK(const ull* w, int k) {
    return w[k < 6 ? k : 10 - k];
}

// Pyramid scratch in (s,d) float2 form
__device__ float2 g_P0[3538944];
__device__ float2 g_P1[884736];
__device__ float g_acc[5 * 96 * 2];

__global__ void zero_acc_kernel() {
    int i = threadIdx.x;
    if (i < 5 * 96 * 2) g_acc[i] = 0.f;
}

// 4-stream SSIM (s=x+y, d=x-y, ss, dd), packed f32x2, 32x32 tile, RY=4.
// h-pass: warp = 2 rows x 16 lane-pairs, LDS.128 via ld.shared.v2.u64,
// column-permuted stores (phys col j & 16+j hold logical cols 2j & 2j+1).
__global__ __launch_bounds__(256)
void ssim_kernel(const float* __restrict__ X, const float* __restrict__ Y,
                 const float2* __restrict__ SDin, float2* __restrict__ SDout,
                 int W, int OW, int scale)
{
    __shared__ float2 sSD[HR][SP];
    __shared__ float4 sH[HR][TILE];
    __shared__ float rs[TYB], rc[TYB];

    const int tx = threadIdx.x, ty = threadIdx.y;
    const int t = ty * 32 + tx;
    const int x0 = blockIdx.x * TILE, y0 = blockIdx.y * TILE;
    const int bc = blockIdx.z;
    const bool interior = (x0 + HR <= W) && (y0 + HR <= W);

    // ---- Load input tile with halo ----
    if (SDin) {
        const float2* Sb = SDin + (size_t)bc * W * W;
        if (interior) {
            for (int i = t; i < HR * 21; i += 256) {
                int r = i / 21, cp = (i - r * 21) * 2;
                float4 v = *(const float4*)&Sb[(size_t)(y0 + r) * W + x0 + cp];
                *(float4*)&sSD[r][cp] = v;
            }
        } else {
            for (int idx = t; idx < HR * HR; idx += 256) {
                int r = idx / HR, c = idx - r * HR;
                int gx = x0 + c, gy = y0 + r;
                float2 v = make_float2(0.f, 0.f);
                if (gx < W && gy < W) v = Sb[(size_t)gy * W + gx];
                sSD[r][c] = v;
            }
        }
    } else {
        const float* Xb = X + (size_t)bc * W * W;
        const float* Yb = Y + (size_t)bc * W * W;
        if (interior) {
            for (int i = t; i < HR * 21; i += 256) {
                int r = i / 21, cp = (i - r * 21) * 2;
                size_t o = (size_t)(y0 + r) * W + x0 + cp;
                float2 xv = *(const float2*)(Xb + o);
                float2 yv = *(const float2*)(Yb + o);
                float4 v = make_float4(xv.x + yv.x, xv.x - yv.x,
                                       xv.y + yv.y, xv.y - yv.y);
                *(float4*)&sSD[r][cp] = v;
            }
        } else {
            for (int idx = t; idx < HR * HR; idx += 256) {
                int r = idx / HR, c = idx - r * HR;
                int gx = x0 + c, gy = y0 + r;
                float xv = 0.f, yv = 0.f;
                if (gx < W && gy < W) {
                    size_t o = (size_t)gy * W + gx;
                    xv = Xb[o]; yv = Yb[o];
                }
                sSD[r][c] = make_float2(xv + yv, xv - yv);
            }
        }
    }
    __syncthreads();

    // ---- Fused 2x2 pool into next-scale (s,d) buffer ----
    if (SDout) {
        int W2 = W >> 1;
        int cx = t & 15, cy = t >> 4;
        int gx2 = (x0 >> 1) + cx, gy2 = (y0 >> 1) + cy;
        if (gx2 < W2 && gy2 < W2) {
            float2 a = sSD[2 * cy][2 * cx],     b = sSD[2 * cy][2 * cx + 1];
            float2 c = sSD[2 * cy + 1][2 * cx], d = sSD[2 * cy + 1][2 * cx + 1];
            float2 o;
            o.x = 0.25f * (a.x + b.x + c.x + d.x);
            o.y = 0.25f * (a.y + b.y + c.y + d.y);
            SDout[(size_t)bc * W2 * W2 + (size_t)gy2 * W2 + gx2] = o;
        }
    }

    ull wpk[6];
    #pragma unroll
    for (int k = 0; k < 6; k++) wpk[k] = pk2(GW[k], GW[k]);

    // ---- Horizontal blur: warp = 2 rows, lane = (half, col-pair j), RX=2 ----
    {
        const int half = tx >> 4;
        const int j = tx & 15;
        #pragma unroll
        for (int rp = 0; rp < HR / 2; rp += TYB) {
            int p = rp + ty;
            if (p < HR / 2) {
                const int r = 2 * p + half;
                ull s0 = 0ULL, q0 = 0ULL, s1 = 0ULL, q1 = 0ULL;
                #pragma unroll
                for (int m = 0; m < 6; m++) {
                    ull pa, pb;
                    lds2(pa, pb, &sSD[r][2 * j + 2 * m]);
                    ull qa = mul2(pa, pa), qb = mul2(pb, pb);
                    s0 = fma2(pa, WPK(wpk, 2 * m), s0);
                    q0 = fma2(qa, WPK(wpk, 2 * m), q0);
                    s1 = fma2(pb, WPK(wpk, 2 * m), s1);
                    q1 = fma2(qb, WPK(wpk, 2 * m), q1);
                    if (m < 5) {
                        s0 = fma2(pb, WPK(wpk, 2 * m + 1), s0);
                        q0 = fma2(qb, WPK(wpk, 2 * m + 1), q0);
                    }
                    if (m > 0) {
                        s1 = fma2(pa, WPK(wpk, 2 * m - 1), s1);
                        q1 = fma2(qa, WPK(wpk, 2 * m - 1), q1);
                    }
                }
                // logical col 2j -> phys col j ; logical col 2j+1 -> phys col 16+j
                sts2(&sH[r][j], s0, q0);
                sts2(&sH[r][16 + j], s1, q1);
            }
        }
    }
    __syncthreads();

    // ---- Vertical blur + SSIM, RY=4 outputs per thread (permuted columns) ----
    ull amu[RY], asg[RY];
    #pragma unroll
    for (int jj = 0; jj < RY; jj++) { amu[jj] = 0ULL; asg[jj] = 0ULL; }
    const int rbase = ty * RY;
    #pragma unroll
    for (int rr = 0; rr < RY - 1 + KS; rr++) {
        ull p01, p23;
        lds2(p01, p23, &sH[rbase + rr][tx]);
        #pragma unroll
        for (int jj = 0; jj < RY; jj++) {
            int k = rr - jj;
            if (k >= 0 && k < KS) {
                amu[jj] = fma2(p01, WPK(wpk, k), amu[jj]);
                asg[jj] = fma2(p23, WPK(wpk, k), asg[jj]);
            }
        }
    }

    float ssum = 0.f, csum = 0.f;
    const int lc = (tx < 16) ? (2 * tx) : (2 * (tx - 16) + 1);  // logical column
    const int ox = x0 + lc;
    #pragma unroll
    for (int jj = 0; jj < RY; jj++) {
        int oy = y0 + rbase + jj;
        if (ox < OW && oy < OW) {
            float ms2, md2, bss, bdd;
            upk2(mul2(amu[jj], amu[jj]), ms2, md2);
            upk2(asg[jj], bss, bdd);
            const float C1 = 6.5025f, C2 = 58.5225f;
            float musum  = 0.5f * (ms2 + md2);
            float mu2x   = 0.5f * (ms2 - md2);
            float sqsum  = 0.5f * (bss + bdd);
            float xy2    = 0.5f * (bss - bdd);
            float A  = (xy2 - mu2x) + C2;
            float B  = (sqsum - musum) + C2;
            float Cn = mu2x + C1;
            float D  = musum + C1;
            float inv = frcp(B * D);
            csum += A * D * inv;
            ssum += A * Cn * inv;
        }
    }

    #pragma unroll
    for (int off = 16; off; off >>= 1) {
        ssum += __shfl_down_sync(0xffffffffu, ssum, off);
        csum += __shfl_down_sync(0xffffffffu, csum, off);
    }
    if (tx == 0) { rs[ty] = ssum; rc[ty] = csum; }
    __syncthreads();
    if (t == 0) {
        float a = 0.f, b = 0.f;
        #pragma unroll
        for (int i = 0; i < TYB; i++) { a += rs[i]; b += rc[i]; }
        atomicAdd(&g_acc[(scale * 96 + bc) * 2 + 0], a);
        atomicAdd(&g_acc[(scale * 96 + bc) * 2 + 1], b);
    }
}

__global__ void finalize_kernel(float* __restrict__ out) {
    __shared__ float sh[96];
    const int i = threadIdx.x;
    const float wts[5]  = {0.0448f, 0.2856f, 0.3001f, 0.2363f, 0.1333f};
    const float cnts[5] = {374.f * 374.f, 182.f * 182.f, 86.f * 86.f, 38.f * 38.f, 14.f * 14.f};
    if (i < 96) {
        float p = 1.f;
        #pragma unroll
        for (int s = 0; s < 5; s++) {
            int comp = (s < 4) ? 1 : 0;
            float m = g_acc[(s * 96 + i) * 2 + comp] / cnts[s];
            m = fmaxf(m, 0.f);
            p *= powf(m, wts[s]);
        }
        sh[i] = p;
    }
    __syncthreads();
    if (i == 0) {
        float s = 0.f;
        for (int j = 0; j < 96; j++) s += sh[j];
        out[0] = 1.f - s / 96.f;
    }
}

extern "C" void kernel_launch(void* const* d_in, const int* in_sizes, int n_in,
                              void* d_out, int out_size)
{
    const float* X = (const float*)d_in[0];
    const float* Y = (const float*)d_in[1];
    float* out = (float*)d_out;

    float2 *P0, *P1;
    cudaGetSymbolAddress((void**)&P0, g_P0);
    cudaGetSymbolAddress((void**)&P1, g_P1);

    zero_acc_kernel<<<1, 960>>>();

    dim3 blk(32, TYB);
    auto mkgrid = [](int OW) {
        int g = (OW + TILE - 1) / TILE;
        return dim3(g, g, 96);
    };

    // scale 0: reads X,Y; pools 192^2 (s,d) into P0
    ssim_kernel<<<mkgrid(374), blk>>>(X, Y, nullptr, P0, 384, 374, 0);
    // scale 1: reads P0; pools 96^2 into P1
    ssim_kernel<<<mkgrid(182), blk>>>(nullptr, nullptr, P0, P1, 192, 182, 1);
    // scale 2: reads P1; pools 48^2 into P0
    ssim_kernel<<<mkgrid(86), blk>>>(nullptr, nullptr, P1, P0, 96, 86, 2);
    // scale 3: reads P0; pools 24^2 into P1
    ssim_kernel<<<mkgrid(38), blk>>>(nullptr, nullptr, P0, P1, 48, 38, 3);
    // scale 4: reads P1; no pool
    ssim_kernel<<<mkgrid(14), blk>>>(nullptr, nullptr, P1, nullptr, 24, 14, 4);

    finalize_kernel<<<1, 96>>>(out);
}